// round 8
// baseline (speedup 1.0000x reference)
#include <cuda_runtime.h>

#define LSEQ 65536
#define NB 32
#define NC 16
#define KW 8
#define THRV 0.25f
#define BETA 15.0f
#define XSC 20.0f

#define PH_STEPS 16                    // steps per phase
#define TILE_STRIDE 20                 // 16 steps + carry(col 16) + pad; 16B-aligned rows
#define WARP_TILE (32 * TILE_STRIDE)   // 640 floats
#define BUF_FLOATS (16 * WARP_TILE)    // 10240 floats per buffer
#define SMEM_FLOATS (2 * BUF_FLOATS)
#define SMEM_BYTES (SMEM_FLOATS * 4)   // 81920 -> 2 blocks/SM

__device__ __forceinline__ float softplusf(float x) {
    return (x > 0.f) ? (x + log1pf(expf(-x))) : log1pf(expf(x));
}

// 256 blocks x 512 threads (16 warps, 2 blocks/SM). block=(b, eighth of L);
// warp w = channel. Lane owns a 256-step chunk at eighth*8192 + lane*256,
// warmed up 32 steps from v=0 (alpha^32~3e-5; spike resets sync exactly).
// 16 phases x 16 steps, DOUBLE-BUFFERED z tiles with ONE barrier per phase:
//   compute(buf[p&1]) -> bar -> drain+logits(buf[p&1]) -> compute(buf[~p&1]) ...
// Everything besides z is derived in the drain:
//   s = (z>=0); vpre = z/BETA + THR; v_prev = (z_prev>=0) ? 0 : vpre_prev
//   I = (vpre - alpha*v_prev) / (1-alpha)        (conv emits (1-alpha)*I)
// Phase-entry carry is stored in z-form at tile col 16.
__global__ __launch_bounds__(512, 2) void snn_fused(
    const float* __restrict__ x,
    const float* __restrict__ wa, const float* __restrict__ wb,
    const float* __restrict__ rta, const float* __restrict__ rtb,
    const float* __restrict__ rga, const float* __restrict__ rgb,
    float* __restrict__ outI, float* __restrict__ outZ,
    float* __restrict__ outS, float* __restrict__ outL)
{
    extern __shared__ float smem[];

    const int b = blockIdx.x >> 3;
    const int eighth = blockIdx.x & 7;
    const int tid = threadIdx.x;
    const int w = tid >> 5;            // channel 0..15
    const int lane = tid & 31;
    const int fidx = w & 7;
    const int isB = w >> 3;

    const float* wrow = (isB ? wb : wa) + fidx * KW;
    const float rt = (isB ? rtb : rta)[fidx];
    const float rg = (isB ? rgb : rga)[0];

    float wo[KW];
    float nsq = 0.f;
#pragma unroll
    for (int k = 0; k < KW; k++) { wo[k] = wrow[k]; nsq = fmaf(wo[k], wo[k], nsq); }
    float norm = sqrtf(nsq);
    if (norm < 1e-8f) norm = 1e-8f;
    const float g = softplusf(rg) + 1e-4f;

    const float alpha = expf(-1.0f / (softplusf(rt) + 1e-4f));
    const float oma = 1.0f - alpha;
    const float inv_oma = 1.0f / oma;
    const float invB = 1.0f / BETA;
    const float nBT = -BETA * THRV;

    const float scale = g * XSC / norm * oma;   // conv directly yields (1-a)*I
#pragma unroll
    for (int k = 0; k < KW; k++) wo[k] *= scale;

    const float* xr = x + ((size_t)(b * 2 + isB) << 16);
    const int p0 = eighth * 8192 + lane * 256;
    const int warm = (p0 == 0) ? 0 : 32;
    int lcur = p0 - warm;

    // sliding window: xw[0..7] = x[l-8 .. l-1]
    float xw[12];
    if (lcur >= 8) {
        float4 a4 = *(const float4*)(xr + lcur - 8);
        float4 b4 = *(const float4*)(xr + lcur - 4);
        xw[0] = a4.x; xw[1] = a4.y; xw[2] = a4.z; xw[3] = a4.w;
        xw[4] = b4.x; xw[5] = b4.y; xw[6] = b4.z; xw[7] = b4.w;
    } else {
#pragma unroll
        for (int k = 0; k < 8; k++) xw[k] = 0.f;
    }

    float vp = 0.f;   // pre-reset membrane of previous step

    // ---- warmup (0 or 32 steps), no emission ----
    for (int gg = 0; gg < (warm >> 2); ++gg) {
        float4 xv = *(const float4*)(xr + lcur);
        xw[8] = xv.x; xw[9] = xv.y; xw[10] = xv.z; xw[11] = xv.w;
#pragma unroll
        for (int k = 0; k < 4; k++) {
            float I = 0.f;
#pragma unroll
            for (int j = 0; j < 8; j++) I = fmaf(wo[j], xw[k + 1 + j], I);
            float cand = fmaf(alpha, vp, I);
            vp = (vp >= THRV) ? I : cand;
        }
#pragma unroll
        for (int j = 0; j < 8; j++) xw[j] = xw[j + 4];
        lcur += 4;
    }

    const size_t seqoff = ((size_t)(b * NC + w)) << 16;
    const int rsub = lane >> 2;          // 0..7 (drain row-in-group)
    const int cq = (lane & 3) * 4;       // 0,4,8,12
    const int cidx = (cq == 0) ? 16 : (cq - 1);   // z_prev source col

#pragma unroll 1
    for (int ph = 0; ph < 16; ++ph) {
        float* buf = smem + (ph & 1) * BUF_FLOATS;
        float* mbuf = buf + w * WARP_TILE;
        float* rowZ = mbuf + lane * TILE_STRIDE;

        // carry in z-form: z_c = BETA*v_post - BETA*THR
        float vpost = (vp >= THRV) ? 0.f : vp;
        rowZ[16] = fmaf(BETA, vpost, nBT);

        // ---- compute 16 steps into buf ----
        float4 xq[4];
#pragma unroll
        for (int gg = 0; gg < 4; gg++) xq[gg] = *(const float4*)(xr + lcur + gg * 4);
#pragma unroll
        for (int gg = 0; gg < 4; gg++) {
            float4 xv = xq[gg];
            xw[8] = xv.x; xw[9] = xv.y; xw[10] = xv.z; xw[11] = xv.w;
            float z4[4];
#pragma unroll
            for (int k = 0; k < 4; k++) {
                float I = 0.f;
#pragma unroll
                for (int j = 0; j < 8; j++) I = fmaf(wo[j], xw[k + 1 + j], I);
                float cand = fmaf(alpha, vp, I);
                vp = (vp >= THRV) ? I : cand;       // vp = vpre_t
                z4[k] = fmaf(BETA, vp, nBT);        // z_t (sign == spike)
            }
            *(float4*)(rowZ + gg * 4) = make_float4(z4[0], z4[1], z4[2], z4[3]);
#pragma unroll
            for (int j = 0; j < 8; j++) xw[j] = xw[j + 4];
        }
        lcur += PH_STEPS;
        __syncthreads();

        // ---- warp-local drain from buf: I,z,s; LDS.128 + STG.128 ----
        const size_t lbase = (size_t)(eighth * 8192 + ph * PH_STEPS);
#pragma unroll
        for (int it = 0; it < 4; ++it) {
            const int r = it * 8 + rsub;
            const float* rw = mbuf + r * TILE_STRIDE;
            float4 z4 = *(const float4*)(rw + cq);
            float zp = rw[cidx];
            float vprev = (zp >= 0.f) ? 0.f : fmaf(zp, invB, THRV);
            float vp0 = fmaf(z4.x, invB, THRV);
            float vp1 = fmaf(z4.y, invB, THRV);
            float vp2 = fmaf(z4.z, invB, THRV);
            float vp3 = fmaf(z4.w, invB, THRV);
            float4 vs;
            vs.x = (z4.x >= 0.f) ? 1.f : 0.f;
            vs.y = (z4.y >= 0.f) ? 1.f : 0.f;
            vs.z = (z4.z >= 0.f) ? 1.f : 0.f;
            vs.w = (z4.w >= 0.f) ? 1.f : 0.f;
            float4 vi;
            vi.x = (vp0 - alpha * vprev) * inv_oma;
            vi.y = (vp1 - alpha * ((z4.x >= 0.f) ? 0.f : vp0)) * inv_oma;
            vi.z = (vp2 - alpha * ((z4.y >= 0.f) ? 0.f : vp1)) * inv_oma;
            vi.w = (vp3 - alpha * ((z4.z >= 0.f) ? 0.f : vp2)) * inv_oma;
            const size_t gi = seqoff + lbase + (size_t)r * 256 + cq;
            __stcs((float4*)(outI + gi), vi);
            __stcs((float4*)(outZ + gi), z4);
            __stcs((float4*)(outS + gi), vs);
        }

        // ---- fused logits: max over 16 channels, 256 threads, float2 ----
        if (tid < 256) {
            const int j = tid >> 3;             // chunk row 0..31
            const int q = (tid & 7) * 2;        // step pair 0..14
            const float* p = buf + j * TILE_STRIDE + q;
            float m0 = p[0], m1 = p[1];
#pragma unroll
            for (int c2 = 1; c2 < 16; ++c2) {
                p += WARP_TILE;
                m0 = fmaxf(m0, p[0]); m1 = fmaxf(m1, p[1]);
            }
            const size_t gl = (((size_t)b) << 16)
                            + (size_t)(eighth * 8192 + j * 256 + ph * PH_STEPS + q);
            __stcs((float2*)(outL + gl), make_float2(m0, m1));
        }
        // no second barrier: next phase writes the other buffer
    }
}

extern "C" void kernel_launch(void* const* d_in, const int* in_sizes, int n_in,
                              void* d_out, int out_size)
{
    const float* x   = (const float*)d_in[0];
    const float* wa  = (const float*)d_in[1];
    const float* wb  = (const float*)d_in[2];
    const float* rta = (const float*)d_in[3];
    const float* rtb = (const float*)d_in[4];
    const float* rga = (const float*)d_in[5];
    const float* rgb = (const float*)d_in[6];

    float* out = (float*)d_out;
    const size_t plane = (size_t)NB * NC * LSEQ;   // 33554432
    float* outI = out;
    float* outZ = out + plane;
    float* outS = out + 2 * plane;
    float* outL = out + 3 * plane;

    cudaFuncSetAttribute(snn_fused, cudaFuncAttributeMaxDynamicSharedMemorySize, SMEM_BYTES);
    snn_fused<<<256, 512, SMEM_BYTES>>>(x, wa, wb, rta, rtb, rga, rgb,
                                        outI, outZ, outS, outL);
}

// round 9
// speedup vs baseline: 1.1542x; 1.1542x over previous
#include <cuda_runtime.h>

#define LSEQ 65536
#define NB 32
#define NC 16
#define KW 8
#define THRV 0.25f
#define BETA 15.0f
#define XSC 20.0f

#define TILE_STRIDE 36                 // 32 steps + carry(col 32) + pad; rows 16B-aligned
#define WARP_TILE (32 * TILE_STRIDE)   // 1152 floats per warp tile
#define SMEM_FLOATS (16 * WARP_TILE)
#define SMEM_BYTES (SMEM_FLOATS * 4)   // 73728 -> 2 blocks/SM

__device__ __forceinline__ float softplusf(float x) {
    return (x > 0.f) ? (x + log1pf(expf(-x))) : log1pf(expf(x));
}

// 256 blocks x 512 threads (16 warps, 2 blocks/SM). block=(b, eighth of L);
// warp w = channel. Lane owns a 256-step chunk at eighth*8192 + lane*256,
// warmed up 32 steps from v=0 (alpha^32~3e-5; spike resets sync exactly).
// 8 phases x 32 steps, single-buffer z tiles, 2 barriers/phase (R6 structure).
// Everything besides z is derived in the drain:
//   s = (z>=0); vpre = z/BETA + THR; v_prev = (z_prev>=0) ? 0 : vpre_prev
//   I = (vpre - alpha*v_prev) / (1-alpha)       (conv emits (1-alpha)*I)
// Phase-entry carry is stored in z-form at tile col 32 -> uniform drain path.
__global__ __launch_bounds__(512, 2) void snn_fused(
    const float* __restrict__ x,
    const float* __restrict__ wa, const float* __restrict__ wb,
    const float* __restrict__ rta, const float* __restrict__ rtb,
    const float* __restrict__ rga, const float* __restrict__ rgb,
    float* __restrict__ outI, float* __restrict__ outZ,
    float* __restrict__ outS, float* __restrict__ outL)
{
    extern __shared__ float smem[];
    float* tZ = smem;                               // [16][32][36]

    const int b = blockIdx.x >> 3;
    const int eighth = blockIdx.x & 7;
    const int tid = threadIdx.x;
    const int w = tid >> 5;            // channel 0..15
    const int lane = tid & 31;
    const int fidx = w & 7;
    const int isB = w >> 3;

    const float* wrow = (isB ? wb : wa) + fidx * KW;
    const float rt = (isB ? rtb : rta)[fidx];
    const float rg = (isB ? rgb : rga)[0];

    float wo[KW];
    float nsq = 0.f;
#pragma unroll
    for (int k = 0; k < KW; k++) { wo[k] = wrow[k]; nsq = fmaf(wo[k], wo[k], nsq); }
    float norm = sqrtf(nsq);
    if (norm < 1e-8f) norm = 1e-8f;
    const float g = softplusf(rg) + 1e-4f;

    const float alpha = expf(-1.0f / (softplusf(rt) + 1e-4f));
    const float oma = 1.0f - alpha;
    const float inv_oma = 1.0f / oma;
    const float invB = 1.0f / BETA;
    const float nBT = -BETA * THRV;

    const float scale = g * XSC / norm * oma;   // conv directly yields (1-a)*I
#pragma unroll
    for (int k = 0; k < KW; k++) wo[k] *= scale;

    const float* xr = x + ((size_t)(b * 2 + isB) << 16);
    const int p0 = eighth * 8192 + lane * 256;
    const int warm = (p0 == 0) ? 0 : 32;
    int lcur = p0 - warm;

    // sliding window: xw[0..7] = x[l-8 .. l-1]
    float xw[12];
    if (lcur >= 8) {
        float4 a4 = *(const float4*)(xr + lcur - 8);
        float4 b4 = *(const float4*)(xr + lcur - 4);
        xw[0] = a4.x; xw[1] = a4.y; xw[2] = a4.z; xw[3] = a4.w;
        xw[4] = b4.x; xw[5] = b4.y; xw[6] = b4.z; xw[7] = b4.w;
    } else {
#pragma unroll
        for (int k = 0; k < 8; k++) xw[k] = 0.f;
    }

    float vp = 0.f;   // pre-reset membrane of previous step

    // ---- warmup (0 or 32 steps), no emission ----
    for (int gg = 0; gg < (warm >> 2); ++gg) {
        float4 xv = *(const float4*)(xr + lcur);
        xw[8] = xv.x; xw[9] = xv.y; xw[10] = xv.z; xw[11] = xv.w;
#pragma unroll
        for (int k = 0; k < 4; k++) {
            float I = 0.f;
#pragma unroll
            for (int j = 0; j < 8; j++) I = fmaf(wo[j], xw[k + 1 + j], I);
            float cand = fmaf(alpha, vp, I);
            vp = (vp >= THRV) ? I : cand;
        }
#pragma unroll
        for (int j = 0; j < 8; j++) xw[j] = xw[j + 4];
        lcur += 4;
    }

    float* mtZ = tZ + w * WARP_TILE;
    float* rowZ = mtZ + lane * TILE_STRIDE;
    const size_t seqoff = ((size_t)(b * NC + w)) << 16;
    const int rsub = lane >> 3;          // 0..3
    const int cq = (lane & 7) * 4;       // 0,4,...,28
    const int cidx = (cq == 0) ? 32 : (cq - 1);   // z_prev source col (32 = z-form carry)

#pragma unroll 1
    for (int ph = 0; ph < 8; ++ph) {
        // carry in z-form: z_c = BETA*v_post - BETA*THR  (sign(z_c) consistent: v_post<THR)
        float vpost = (vp >= THRV) ? 0.f : vp;
        rowZ[32] = fmaf(BETA, vpost, nBT);

        // ---- compute 32 steps into own tile ----
#pragma unroll
        for (int sp = 0; sp < 2; ++sp) {
            float4 xq[4];
#pragma unroll
            for (int gg = 0; gg < 4; gg++) xq[gg] = *(const float4*)(xr + lcur + gg * 4);
#pragma unroll
            for (int gg = 0; gg < 4; gg++) {
                float4 xv = xq[gg];
                xw[8] = xv.x; xw[9] = xv.y; xw[10] = xv.z; xw[11] = xv.w;
                float z4[4];
#pragma unroll
                for (int k = 0; k < 4; k++) {
                    float I = 0.f;
#pragma unroll
                    for (int j = 0; j < 8; j++) I = fmaf(wo[j], xw[k + 1 + j], I);
                    float cand = fmaf(alpha, vp, I);
                    vp = (vp >= THRV) ? I : cand;       // vp = vpre_t
                    z4[k] = fmaf(BETA, vp, nBT);        // z_t (sign == spike)
                }
                *(float4*)(rowZ + sp * 16 + gg * 4) = make_float4(z4[0], z4[1], z4[2], z4[3]);
#pragma unroll
                for (int j = 0; j < 8; j++) xw[j] = xw[j + 4];
            }
            lcur += 16;
        }
        __syncthreads();

        // ---- warp-local drain: I,z,s from z tile; LDS.128 + STG.128 ----
        const size_t lbase = (size_t)(eighth * 8192 + ph * 32);
#pragma unroll
        for (int it = 0; it < 8; ++it) {
            const int r = it * 4 + rsub;
            const float* rw = mtZ + r * TILE_STRIDE;
            float4 z4 = *(const float4*)(rw + cq);
            float zp = rw[cidx];
            float vprev = (zp >= 0.f) ? 0.f : fmaf(zp, invB, THRV);
            float vp0 = fmaf(z4.x, invB, THRV);
            float vp1 = fmaf(z4.y, invB, THRV);
            float vp2 = fmaf(z4.z, invB, THRV);
            float vp3 = fmaf(z4.w, invB, THRV);
            float4 vs;
            vs.x = (z4.x >= 0.f) ? 1.f : 0.f;
            vs.y = (z4.y >= 0.f) ? 1.f : 0.f;
            vs.z = (z4.z >= 0.f) ? 1.f : 0.f;
            vs.w = (z4.w >= 0.f) ? 1.f : 0.f;
            float4 vi;
            vi.x = (vp0 - alpha * vprev) * inv_oma;
            vi.y = (vp1 - alpha * ((z4.x >= 0.f) ? 0.f : vp0)) * inv_oma;
            vi.z = (vp2 - alpha * ((z4.y >= 0.f) ? 0.f : vp1)) * inv_oma;
            vi.w = (vp3 - alpha * ((z4.z >= 0.f) ? 0.f : vp2)) * inv_oma;
            const size_t gi = seqoff + lbase + (size_t)r * 256 + cq;
            __stcs((float4*)(outI + gi), vi);
            __stcs((float4*)(outZ + gi), z4);
            __stcs((float4*)(outS + gi), vs);
        }

        // ---- fused logits: max over 16 channels, 256 threads, float4 ----
        if (tid < 256) {
            const int j = tid >> 3;             // chunk row 0..31
            const int q = (tid & 7) * 4;        // step quad
            const float* p = tZ + j * TILE_STRIDE + q;
            float4 m = *(const float4*)p;
#pragma unroll
            for (int c2 = 1; c2 < 16; ++c2) {
                p += WARP_TILE;
                float4 t4 = *(const float4*)p;
                m.x = fmaxf(m.x, t4.x); m.y = fmaxf(m.y, t4.y);
                m.z = fmaxf(m.z, t4.z); m.w = fmaxf(m.w, t4.w);
            }
            const size_t gl = (((size_t)b) << 16)
                            + (size_t)(eighth * 8192 + j * 256 + ph * 32 + q);
            __stcs((float4*)(outL + gl), m);
        }
        __syncthreads();
    }
}

extern "C" void kernel_launch(void* const* d_in, const int* in_sizes, int n_in,
                              void* d_out, int out_size)
{
    const float* x   = (const float*)d_in[0];
    const float* wa  = (const float*)d_in[1];
    const float* wb  = (const float*)d_in[2];
    const float* rta = (const float*)d_in[3];
    const float* rtb = (const float*)d_in[4];
    const float* rga = (const float*)d_in[5];
    const float* rgb = (const float*)d_in[6];

    float* out = (float*)d_out;
    const size_t plane = (size_t)NB * NC * LSEQ;   // 33554432
    float* outI = out;
    float* outZ = out + plane;
    float* outS = out + 2 * plane;
    float* outL = out + 3 * plane;

    cudaFuncSetAttribute(snn_fused, cudaFuncAttributeMaxDynamicSharedMemorySize, SMEM_BYTES);
    snn_fused<<<256, 512, SMEM_BYTES>>>(x, wa, wb, rta, rtb, rga, rgb,
                                        outI, outZ, outS, outL);
}

// round 10
// speedup vs baseline: 1.3506x; 1.1702x over previous
#include <cuda_runtime.h>

#define LSEQ 65536
#define NB 32
#define NC 16
#define KW 8
#define THRV 0.25f
#define BETA 15.0f
#define XSC 20.0f

#define TILE_STRIDE 36                 // 32 steps + carry(col 32) + pad; rows 16B-aligned
#define WARP_TILE (32 * TILE_STRIDE)   // 1152 floats per warp z tile
#define XROW_FLOATS (32 * 36)          // 32 pieces x 32 floats, stride 36
#define SMEM_FLOATS (16 * WARP_TILE + 2 * XROW_FLOATS)
#define SMEM_BYTES (SMEM_FLOATS * 4)   // 82944 -> 2 blocks/SM

__device__ __forceinline__ float softplusf(float x) {
    return (x > 0.f) ? (x + log1pf(expf(-x))) : log1pf(expf(x));
}

// 256 blocks x 512 threads (16 warps, 2 blocks/SM). block=(b, eighth of L);
// warp w = channel. Lane owns a 256-step chunk at eighth*8192 + lane*256,
// warmed up 32 steps from v=0 (alpha^32~3e-5; spike resets sync exactly).
// 8 phases x 32 steps. Key change vs R6/R9: x is STAGED through smem with a
// coalesced gather (nL=4 lines per LDG.128 instead of the 32-line per-lane
// gather that saturated L1tex wavefronts). Stage for phase p+1 is issued
// right after bar1 so its LDG latency overlaps the drain of phase p.
// Drain derives everything from z: s=(z>=0); vpre=z/BETA+THR;
// v_prev=(z_prev>=0)?0:vpre_prev; I=(vpre-alpha*v_prev)/(1-alpha).
// Phase-entry carry stored in z-form at tile col 32. Logits fused.
__global__ __launch_bounds__(512, 2) void snn_fused(
    const float* __restrict__ x,
    const float* __restrict__ wa, const float* __restrict__ wb,
    const float* __restrict__ rta, const float* __restrict__ rtb,
    const float* __restrict__ rga, const float* __restrict__ rgb,
    float* __restrict__ outI, float* __restrict__ outZ,
    float* __restrict__ outS, float* __restrict__ outL)
{
    extern __shared__ float smem[];
    float* tZ = smem;                          // [16][32][36]
    float* sx = smem + 16 * WARP_TILE;         // [2][32][36]

    const int b = blockIdx.x >> 3;
    const int eighth = blockIdx.x & 7;
    const int tid = threadIdx.x;
    const int w = tid >> 5;            // channel 0..15
    const int lane = tid & 31;
    const int fidx = w & 7;
    const int isB = w >> 3;

    const float* wrow = (isB ? wb : wa) + fidx * KW;
    const float rt = (isB ? rtb : rta)[fidx];
    const float rg = (isB ? rgb : rga)[0];

    float wo[KW];
    float nsq = 0.f;
#pragma unroll
    for (int k = 0; k < KW; k++) { wo[k] = wrow[k]; nsq = fmaf(wo[k], wo[k], nsq); }
    float norm = sqrtf(nsq);
    if (norm < 1e-8f) norm = 1e-8f;
    const float g = softplusf(rg) + 1e-4f;

    const float alpha = expf(-1.0f / (softplusf(rt) + 1e-4f));
    const float oma = 1.0f - alpha;
    const float inv_oma = 1.0f / oma;
    const float invB = 1.0f / BETA;
    const float nBT = -BETA * THRV;

    const float scale = g * XSC / norm * oma;   // conv directly yields (1-a)*I
#pragma unroll
    for (int k = 0; k < KW; k++) wo[k] *= scale;

    const float* xr = x + ((size_t)(b * 2 + isB) << 16);
    const int p0 = eighth * 8192 + lane * 256;
    const int warm = (p0 == 0) ? 0 : 32;
    int lcur = p0 - warm;

    // x-stage mapping: threads 0-255 -> x row 0, 256-511 -> x row 1.
    // piece p = lane chunk p; thread loads 16B of piece p at quad q.
    const int sr = tid >> 8;
    const int tt = tid & 255;
    const int spiece = tt >> 3;
    const int sq = (tt & 7) * 4;
    const float* sgbase = x + ((size_t)(b * 2 + sr) << 16)
                        + (size_t)(eighth * 8192 + spiece * 256 + sq);
    float* sxdst = sx + sr * XROW_FLOATS + spiece * 36 + sq;

    // sliding window: xw[0..7] = x[l-8 .. l-1]
    float xw[12];
    if (lcur >= 8) {
        float4 a4 = *(const float4*)(xr + lcur - 8);
        float4 b4 = *(const float4*)(xr + lcur - 4);
        xw[0] = a4.x; xw[1] = a4.y; xw[2] = a4.z; xw[3] = a4.w;
        xw[4] = b4.x; xw[5] = b4.y; xw[6] = b4.z; xw[7] = b4.w;
    } else {
#pragma unroll
        for (int k = 0; k < 8; k++) xw[k] = 0.f;
    }

    float vp = 0.f;   // pre-reset membrane of previous step

    // ---- warmup (0 or 32 steps), direct LDG, no emission ----
    for (int gg = 0; gg < (warm >> 2); ++gg) {
        float4 xv = *(const float4*)(xr + lcur);
        xw[8] = xv.x; xw[9] = xv.y; xw[10] = xv.z; xw[11] = xv.w;
#pragma unroll
        for (int k = 0; k < 4; k++) {
            float I = 0.f;
#pragma unroll
            for (int j = 0; j < 8; j++) I = fmaf(wo[j], xw[k + 1 + j], I);
            float cand = fmaf(alpha, vp, I);
            vp = (vp >= THRV) ? I : cand;
        }
#pragma unroll
        for (int j = 0; j < 8; j++) xw[j] = xw[j + 4];
        lcur += 4;
    }

    // stage x for phase 0
    *(float4*)sxdst = *(const float4*)(sgbase);
    __syncthreads();

    float* mtZ = tZ + w * WARP_TILE;
    float* rowZ = mtZ + lane * TILE_STRIDE;
    const float* sxrow = sx + isB * XROW_FLOATS + lane * 36;
    const size_t seqoff = ((size_t)(b * NC + w)) << 16;
    const int rsub = lane >> 3;          // 0..3
    const int cq = (lane & 7) * 4;       // 0,4,...,28
    const int cidx = (cq == 0) ? 32 : (cq - 1);   // z_prev source col

#pragma unroll 1
    for (int ph = 0; ph < 8; ++ph) {
        // carry in z-form: z_c = BETA*v_post - BETA*THR
        float vpost = (vp >= THRV) ? 0.f : vp;
        rowZ[32] = fmaf(BETA, vpost, nBT);

        // ---- compute 32 steps from staged x (LDS.128, conflict-free) ----
#pragma unroll
        for (int sp = 0; sp < 2; ++sp) {
            float4 xq[4];
#pragma unroll
            for (int gg = 0; gg < 4; gg++)
                xq[gg] = *(const float4*)(sxrow + sp * 16 + gg * 4);
#pragma unroll
            for (int gg = 0; gg < 4; gg++) {
                float4 xv = xq[gg];
                xw[8] = xv.x; xw[9] = xv.y; xw[10] = xv.z; xw[11] = xv.w;
                float z4[4];
#pragma unroll
                for (int k = 0; k < 4; k++) {
                    float I = 0.f;
#pragma unroll
                    for (int j = 0; j < 8; j++) I = fmaf(wo[j], xw[k + 1 + j], I);
                    float cand = fmaf(alpha, vp, I);
                    vp = (vp >= THRV) ? I : cand;       // vp = vpre_t
                    z4[k] = fmaf(BETA, vp, nBT);        // z_t (sign == spike)
                }
                *(float4*)(rowZ + sp * 16 + gg * 4) = make_float4(z4[0], z4[1], z4[2], z4[3]);
#pragma unroll
                for (int j = 0; j < 8; j++) xw[j] = xw[j + 4];
            }
        }
        __syncthreads();

        // issue next phase's x gather early; STS after drain+logits
        float4 stg;
        const bool do_stage = (ph < 7);
        if (do_stage) stg = *(const float4*)(sgbase + (ph + 1) * 32);

        // ---- warp-local drain: I,z,s from z tile; LDS.128 + STG.128 ----
        const size_t lbase = (size_t)(eighth * 8192 + ph * 32);
#pragma unroll
        for (int it = 0; it < 8; ++it) {
            const int r = it * 4 + rsub;
            const float* rw = mtZ + r * TILE_STRIDE;
            float4 z4 = *(const float4*)(rw + cq);
            float zp = rw[cidx];
            float vprev = (zp >= 0.f) ? 0.f : fmaf(zp, invB, THRV);
            float vp0 = fmaf(z4.x, invB, THRV);
            float vp1 = fmaf(z4.y, invB, THRV);
            float vp2 = fmaf(z4.z, invB, THRV);
            float vp3 = fmaf(z4.w, invB, THRV);
            float4 vs;
            vs.x = (z4.x >= 0.f) ? 1.f : 0.f;
            vs.y = (z4.y >= 0.f) ? 1.f : 0.f;
            vs.z = (z4.z >= 0.f) ? 1.f : 0.f;
            vs.w = (z4.w >= 0.f) ? 1.f : 0.f;
            float4 vi;
            vi.x = (vp0 - alpha * vprev) * inv_oma;
            vi.y = (vp1 - alpha * ((z4.x >= 0.f) ? 0.f : vp0)) * inv_oma;
            vi.z = (vp2 - alpha * ((z4.y >= 0.f) ? 0.f : vp1)) * inv_oma;
            vi.w = (vp3 - alpha * ((z4.z >= 0.f) ? 0.f : vp2)) * inv_oma;
            const size_t gi = seqoff + lbase + (size_t)r * 256 + cq;
            __stcs((float4*)(outI + gi), vi);
            __stcs((float4*)(outZ + gi), z4);
            __stcs((float4*)(outS + gi), vs);
        }

        // ---- fused logits: max over 16 channels, 256 threads, float4 ----
        if (tid < 256) {
            const int j = tid >> 3;             // chunk row 0..31
            const int q = (tid & 7) * 4;        // step quad
            const float* p = tZ + j * TILE_STRIDE + q;
            float4 m = *(const float4*)p;
#pragma unroll
            for (int c2 = 1; c2 < 16; ++c2) {
                p += WARP_TILE;
                float4 t4 = *(const float4*)p;
                m.x = fmaxf(m.x, t4.x); m.y = fmaxf(m.y, t4.y);
                m.z = fmaxf(m.z, t4.z); m.w = fmaxf(m.w, t4.w);
            }
            const size_t gl = (((size_t)b) << 16)
                            + (size_t)(eighth * 8192 + j * 256 + ph * 32 + q);
            __stcs((float4*)(outL + gl), m);
        }

        if (do_stage) *(float4*)sxdst = stg;
        __syncthreads();
    }
}

extern "C" void kernel_launch(void* const* d_in, const int* in_sizes, int n_in,
                              void* d_out, int out_size)
{
    const float* x   = (const float*)d_in[0];
    const float* wa  = (const float*)d_in[1];
    const float* wb  = (const float*)d_in[2];
    const float* rta = (const float*)d_in[3];
    const float* rtb = (const float*)d_in[4];
    const float* rga = (const float*)d_in[5];
    const float* rgb = (const float*)d_in[6];

    float* out = (float*)d_out;
    const size_t plane = (size_t)NB * NC * LSEQ;   // 33554432
    float* outI = out;
    float* outZ = out + plane;
    float* outS = out + 2 * plane;
    float* outL = out + 3 * plane;

    cudaFuncSetAttribute(snn_fused, cudaFuncAttributeMaxDynamicSharedMemorySize, SMEM_BYTES);
    snn_fused<<<256, 512, SMEM_BYTES>>>(x, wa, wb, rta, rtb, rga, rgb,
                                        outI, outZ, outS, outL);
}